// round 8
// baseline (speedup 1.0000x reference)
#include <cuda_runtime.h>
#include <cuda_bf16.h>
#include <cstdint>

#define VOCAB   8192
#define EMB     256
#define NROWS   16384

// ---------------- global scratch ----------------
__device__ float g_e_half[VOCAB];
__device__ __align__(128) int8_t g_zq[(size_t)NROWS * EMB];
__device__ __align__(128) int8_t g_eq[(size_t)VOCAB * EMB];
__device__ int g_cand[NROWS * 4];
__device__ int g_amax_z = 0;   // float bits; atomicMax idempotent across replays
__device__ int g_amax_e = 0;

__device__ __forceinline__ uint32_t smem_u32(const void* p) {
    uint32_t a;
    asm("{ .reg .u64 t; cvta.to.shared.u64 t, %1; cvt.u32.u64 %0, t; }" : "=r"(a) : "l"(p));
    return a;
}
__device__ __forceinline__ void cp16(uint32_t dst, const void* src) {
    asm volatile("cp.async.cg.shared.global [%0], [%1], 16;" :: "r"(dst), "l"(src) : "memory");
}

#define IMMA16832(c, a, bv0, bv1) \
    asm volatile("mma.sync.aligned.m16n8k32.row.col.s32.s8.s8.s32 " \
        "{%0,%1,%2,%3}, {%4,%5,%6,%7}, {%8,%9}, {%0,%1,%2,%3};" \
        : "+r"((c)[0]), "+r"((c)[1]), "+r"((c)[2]), "+r"((c)[3]) \
        : "r"((a)[0]), "r"((a)[1]), "r"((a)[2]), "r"((a)[3]), "r"(bv0), "r"(bv1))

#define LDMX4(r, addr) \
    asm volatile("ldmatrix.sync.aligned.m8n8.x4.shared.b16 {%0,%1,%2,%3}, [%4];" \
        : "=r"((r)[0]), "=r"((r)[1]), "=r"((r)[2]), "=r"((r)[3]) : "r"(addr))

// ---------------- prep kernels ----------------
__global__ void vq_amax_kernel(const float* __restrict__ z, const float* __restrict__ cb) {
    const int stride = gridDim.x * blockDim.x;
    int i = blockIdx.x * blockDim.x + threadIdx.x;
    float mz = 0.f, me = 0.f;
    for (int j = i; j < NROWS * EMB / 4; j += stride) {
        float4 v = ((const float4*)z)[j];
        mz = fmaxf(mz, fmaxf(fmaxf(fabsf(v.x), fabsf(v.y)), fmaxf(fabsf(v.z), fabsf(v.w))));
    }
    for (int j = i; j < VOCAB * EMB / 4; j += stride) {
        float4 v = ((const float4*)cb)[j];
        me = fmaxf(me, fmaxf(fmaxf(fabsf(v.x), fabsf(v.y)), fmaxf(fabsf(v.z), fabsf(v.w))));
    }
    #pragma unroll
    for (int o = 16; o > 0; o >>= 1) {
        mz = fmaxf(mz, __shfl_xor_sync(0xffffffffu, mz, o));
        me = fmaxf(me, __shfl_xor_sync(0xffffffffu, me, o));
    }
    if ((threadIdx.x & 31) == 0) {
        atomicMax(&g_amax_z, __float_as_int(mz));
        atomicMax(&g_amax_e, __float_as_int(me));
    }
}

__device__ __forceinline__ int8_t q8(float v, float inv) {
    int q = __float2int_rn(v * inv);
    return (int8_t)max(-127, min(127, q));
}

__global__ void vq_quant_kernel(const float* __restrict__ z, const float* __restrict__ cb) {
    const float az = __int_as_float(g_amax_z), ae = __int_as_float(g_amax_e);
    const float iz = az > 0.f ? 127.f / az : 0.f;
    const float ie = ae > 0.f ? 127.f / ae : 0.f;
    const int NZ4 = NROWS * EMB / 4;
    const int NE4 = VOCAB * EMB / 4;
    int i = blockIdx.x * blockDim.x + threadIdx.x;
    if (i < NZ4) {
        float4 v = ((const float4*)z)[i];
        char4 c; c.x = q8(v.x, iz); c.y = q8(v.y, iz); c.z = q8(v.z, iz); c.w = q8(v.w, iz);
        ((char4*)g_zq)[i] = c;
    } else if (i < NZ4 + NE4) {
        int j = i - NZ4;
        float4 v = ((const float4*)cb)[j];
        char4 c; c.x = q8(v.x, ie); c.y = q8(v.y, ie); c.z = q8(v.z, ie); c.w = q8(v.w, ie);
        ((char4*)g_eq)[j] = c;
    }
}

__global__ void vq_prep_kernel(const float* __restrict__ cb, float* __restrict__ ref_out) {
    int gtid = blockIdx.x * blockDim.x + threadIdx.x;
    int warp = gtid >> 5;
    int lane = threadIdx.x & 31;
    if (warp < VOCAB) {
        const float4* row = (const float4*)(cb + (size_t)warp * EMB);
        float4 a = row[lane];
        float4 b = row[lane + 32];
        float s = a.x*a.x + a.y*a.y + a.z*a.z + a.w*a.w
                + b.x*b.x + b.y*b.y + b.z*b.z + b.w*b.w;
        #pragma unroll
        for (int o = 16; o > 0; o >>= 1) s += __shfl_xor_sync(0xffffffffu, s, o);
        if (lane == 0) g_e_half[warp] = 0.5f * s;
    }
    if (gtid < VOCAB) ref_out[gtid] = 0.0f;
}

// ---------------- phase 1: IMMA GEMM + top-candidate select ----------------
#define GCH     32                      // codes per chunk
#define NCHUNKS (VOCAB / GCH)           // 256
#define BBUF    8192                    // bytes per B stage (32 codes x 256B)
#define SM_EH   24576                   // after 3 B stages
#define SMEM_GB (SM_EH + VOCAB * 4)     // 57344

#define TOP2(s_, c_, v1, i1, v2, i2) { float _t = (s_); \
    if (_t > (v2)) { if (_t > (v1)) { (v2)=(v1); (i2)=(i1); (v1)=_t; (i1)=(c_); } \
                     else          { (v2)=_t;  (i2)=(c_); } } }

#define INS4(s_, c_) { float _u = (s_); int _d = (c_); \
    if (_u > w3) { \
        if (_u > w1) { \
            if (_u > w0) { w3=w2;q3=q2; w2=w1;q2=q1; w1=w0;q1=q0; w0=_u;q0=_d; } \
            else         { w3=w2;q3=q2; w2=w1;q2=q1; w1=_u;q1=_d; } \
        } else { \
            if (_u > w2) { w3=w2;q3=q2; w2=_u;q2=_d; } \
            else         { w3=_u;q3=_d; } \
        } } }

__global__ void __launch_bounds__(256, 1) vq_gemm_kernel() {
    extern __shared__ char sm[];
    const uint32_t sb = smem_u32(sm);
    const int tid  = threadIdx.x;
    const int lane = tid & 31;
    const int warp = tid >> 5;      // 0..7, each owns 16 rows
    const int blk  = blockIdx.x;

    const float gscale = (__int_as_float(g_amax_z) / 127.f) * (__int_as_float(g_amax_e) / 127.f);

    // ---- stage this CTA's 128 z rows (256B each) swizzled into smem ----
    {
        const char* src = (const char*)g_zq + (size_t)blk * 128 * 256;
        #pragma unroll
        for (int j = 0; j < 8; ++j) {
            int u = tid + j * 256;      // 0..2047 granules of 16B
            int n = u >> 4, g = u & 15;
            cp16(sb + n * 256 + ((g ^ (n & 7)) << 4), src + (size_t)u * 16);
        }
        asm volatile("cp.async.commit_group;" ::: "memory");
        asm volatile("cp.async.wait_group 0;" ::: "memory");
        __syncthreads();
    }

    // ---- resident A fragments: 8 k-blocks x 4 regs (16 rows/warp, k32 int8) ----
    uint32_t A[8][4];
    {
        const int r = warp * 16 + (lane & 15);
        #pragma unroll
        for (int kb = 0; kb < 8; ++kb) {
            uint32_t addr = sb + r * 256 + (((2 * kb + (lane >> 4)) ^ (r & 7)) << 4);
            LDMX4(A[kb], addr);
        }
    }
    __syncthreads();   // smem reusable

    // ---- prologue: first two B chunks + e_half table ----
    {
        #pragma unroll
        for (int s = 0; s < 2; ++s) {
            const char* src = (const char*)g_eq + (size_t)s * GCH * 256;
            uint32_t dstb = sb + s * BBUF;
            #pragma unroll
            for (int j = 0; j < 2; ++j) {
                int u = tid + j * 256;  // 0..511
                int n = u >> 4, g = u & 15;
                cp16(dstb + n * 256 + ((g ^ (n & 7)) << 4), src + (size_t)u * 16);
            }
            asm volatile("cp.async.commit_group;" ::: "memory");
        }
        for (int i = tid; i < VOCAB; i += 256)
            *(float*)(sm + SM_EH + i * 4) = g_e_half[i];
    }

    int acc[4][4];
    #pragma unroll
    for (int nb = 0; nb < 4; ++nb)
        #pragma unroll
        for (int q = 0; q < 4; ++q) acc[nb][q] = 0;

    float tv1[2], tv2[2];
    int   ti1[2], ti2[2];
    #pragma unroll
    for (int s = 0; s < 2; ++s) { tv1[s] = -3.4e38f; tv2[s] = -3.4e38f; ti1[s] = 0; ti2[s] = 0; }

    const int nbase = ((lane >> 4) & 1) * 8 + (lane & 7);
    const uint32_t brow0 = (uint32_t)nbase * 256;
    const uint32_t brow1 = (uint32_t)(nbase + 16) * 256;
    const int gb = (lane >> 3) & 1;
    const int sw = lane & 7;

    for (int ch = 0; ch < NCHUNKS; ++ch) {
        if (ch >= NCHUNKS - 1) asm volatile("cp.async.wait_group 0;" ::: "memory");
        else                   asm volatile("cp.async.wait_group 1;" ::: "memory");
        __syncthreads();

        const uint32_t bb = sb + (uint32_t)(ch % 3) * BBUF;

        // B register double-buffer
        uint32_t B0[2][4], B1[2][4];
        {
            const uint32_t go0 = (uint32_t)((gb ^ sw) << 4);
            LDMX4(B0[0], bb + brow0 + go0);
            LDMX4(B1[0], bb + brow1 + go0);
        }
        #pragma unroll
        for (int kb = 0; kb < 8; ++kb) {
            const int p = kb & 1;
            if (kb < 7) {
                const uint32_t go = (uint32_t)(((2 * (kb + 1) + gb) ^ sw) << 4);
                LDMX4(B0[p ^ 1], bb + brow0 + go);
                LDMX4(B1[p ^ 1], bb + brow1 + go);
            }
            IMMA16832(acc[0], A[kb], B0[p][0], B0[p][1]);
            IMMA16832(acc[1], A[kb], B0[p][2], B0[p][3]);
            IMMA16832(acc[2], A[kb], B1[p][0], B1[p][1]);
            IMMA16832(acc[3], A[kb], B1[p][2], B1[p][3]);
        }

        // epilogue: descale, fold -0.5||e||^2, per-row top-2, reset acc
        const int c0 = ch * GCH + 2 * (lane & 3);
        #pragma unroll
        for (int nb = 0; nb < 4; ++nb) {
            const int ca = c0 + nb * 8;
            const float2 eh = *(const float2*)(sm + SM_EH + (size_t)ca * 4);
            TOP2((float)acc[nb][0] * gscale - eh.x, ca,     tv1[0], ti1[0], tv2[0], ti2[0]);
            TOP2((float)acc[nb][1] * gscale - eh.y, ca + 1, tv1[0], ti1[0], tv2[0], ti2[0]);
            TOP2((float)acc[nb][2] * gscale - eh.x, ca,     tv1[1], ti1[1], tv2[1], ti2[1]);
            TOP2((float)acc[nb][3] * gscale - eh.y, ca + 1, tv1[1], ti1[1], tv2[1], ti2[1]);
            acc[nb][0] = 0; acc[nb][1] = 0; acc[nb][2] = 0; acc[nb][3] = 0;
        }

        // prefetch chunk ch+2
        if (ch + 2 < NCHUNKS) {
            const char* src = (const char*)g_eq + (size_t)(ch + 2) * GCH * 256;
            uint32_t dstb = sb + (uint32_t)((ch + 2) % 3) * BBUF;
            #pragma unroll
            for (int j = 0; j < 2; ++j) {
                int u = tid + j * 256;
                int n = u >> 4, g = u & 15;
                cp16(dstb + n * 256 + ((g ^ (n & 7)) << 4), src + (size_t)u * 16);
            }
            asm volatile("cp.async.commit_group;" ::: "memory");
        }
    }

    // ---- merge per-thread top-2 across the quad -> top-4 per row ----
    #pragma unroll
    for (int slot = 0; slot < 2; ++slot) {
        float w0 = tv1[slot], w1 = tv2[slot], w2 = -3.4e38f, w3 = -3.4e38f;
        int   q0 = ti1[slot], q1 = ti2[slot], q2 = 0, q3 = 0;
        #pragma unroll
        for (int d = 1; d <= 2; d <<= 1) {
            float o0 = __shfl_xor_sync(0xffffffffu, w0, d);
            float o1 = __shfl_xor_sync(0xffffffffu, w1, d);
            float o2 = __shfl_xor_sync(0xffffffffu, w2, d);
            float o3 = __shfl_xor_sync(0xffffffffu, w3, d);
            int   p0 = __shfl_xor_sync(0xffffffffu, q0, d);
            int   p1 = __shfl_xor_sync(0xffffffffu, q1, d);
            int   p2 = __shfl_xor_sync(0xffffffffu, q2, d);
            int   p3 = __shfl_xor_sync(0xffffffffu, q3, d);
            INS4(o0, p0); INS4(o1, p1); INS4(o2, p2); INS4(o3, p3);
        }
        if ((lane & 3) == 0) {
            const int row = blk * 128 + warp * 16 + slot * 8 + (lane >> 2);
            g_cand[row * 4 + 0] = q0;
            g_cand[row * 4 + 1] = q1;
            g_cand[row * 4 + 2] = q2;
            g_cand[row * 4 + 3] = q3;
        }
    }
}

// ---------------- phase 2: exact fp32 rescore + outputs --------------------
__global__ void __launch_bounds__(256) vq_rescore_kernel(
    const float* __restrict__ z, const float* __restrict__ cb,
    float* __restrict__ tok, float* __restrict__ zq, float* __restrict__ ref) {
    const int warp = threadIdx.x >> 5, lane = threadIdx.x & 31;
    const int row  = blockIdx.x * 8 + warp;

    int cand[4];
    #pragma unroll
    for (int k = 0; k < 4; ++k) cand[k] = g_cand[row * 4 + k];

    const float4* zr = (const float4*)(z + (size_t)row * EMB);
    const float4 z0 = zr[lane * 2], z1 = zr[lane * 2 + 1];

    float4 e0[4], e1[4];
    #pragma unroll
    for (int k = 0; k < 4; ++k) {
        const float4* er = (const float4*)(cb + (size_t)cand[k] * EMB);
        e0[k] = er[lane * 2];
        e1[k] = er[lane * 2 + 1];
    }
    float eh[4];
    #pragma unroll
    for (int k = 0; k < 4; ++k) eh[k] = g_e_half[cand[k]];

    float best = -3.4e38f;
    int   bi   = 0x7fffffff;
    #pragma unroll
    for (int k = 0; k < 4; ++k) {
        float d = z0.x*e0[k].x + z0.y*e0[k].y + z0.z*e0[k].z + z0.w*e0[k].w
                + z1.x*e1[k].x + z1.y*e1[k].y + z1.z*e1[k].z + z1.w*e1[k].w;
        #pragma unroll
        for (int o = 16; o > 0; o >>= 1) d += __shfl_xor_sync(0xffffffffu, d, o);
        const float s = d - eh[k];
        const int   c = cand[k];
        if (s > best || (s == best && c < bi)) { best = s; bi = c; }
    }
    tok[row] = (float)bi;
    if (lane == 0) atomicAdd(&ref[bi], 1.0f);
    const float4* eb = (const float4*)(cb + (size_t)bi * EMB);
    float4* o = (float4*)(zq + (size_t)row * EMB);
    o[lane * 2]     = eb[lane * 2];
    o[lane * 2 + 1] = eb[lane * 2 + 1];
}

// ---------------- launch ----------------------------------------------------
extern "C" void kernel_launch(void* const* d_in, const int* in_sizes, int n_in,
                              void* d_out, int out_size) {
    const float* z;
    const float* cb;
    if (in_sizes[0] == NROWS * EMB) { z = (const float*)d_in[0]; cb = (const float*)d_in[1]; }
    else                            { z = (const float*)d_in[1]; cb = (const float*)d_in[0]; }

    float* out = (float*)d_out;
    float* tok = out;
    float* zq  = out + NROWS;
    float* ref = out + NROWS + (size_t)NROWS * EMB;

    cudaFuncSetAttribute(vq_gemm_kernel, cudaFuncAttributeMaxDynamicSharedMemorySize, SMEM_GB);

    vq_amax_kernel<<<592, 256>>>(z, cb);
    const int nconv = (NROWS * EMB / 4) + (VOCAB * EMB / 4);
    vq_quant_kernel<<<(nconv + 255) / 256, 256>>>(z, cb);
    vq_prep_kernel<<<(VOCAB * 32) / 256, 256>>>(cb, ref);
    vq_gemm_kernel<<<NROWS / 128, 256, SMEM_GB>>>();
    vq_rescore_kernel<<<NROWS / 8, 256>>>(z, cb, tok, zq, ref);
}

// round 9
// speedup vs baseline: 2.4357x; 2.4357x over previous
#include <cuda_runtime.h>
#include <cuda_fp16.h>
#include <cstdint>

#define VOCAB   8192
#define EMB     256
#define NROWS   16384

// ---------------- global scratch ----------------
__device__ float g_e_half[VOCAB];
__device__ __align__(128) __half g_zh[(size_t)NROWS * EMB];
__device__ __align__(128) __half g_eh16[(size_t)VOCAB * EMB];
__device__ int g_cand[NROWS * 4];

__device__ __forceinline__ uint32_t smem_u32(const void* p) {
    uint32_t a;
    asm("{ .reg .u64 t; cvta.to.shared.u64 t, %1; cvt.u32.u64 %0, t; }" : "=r"(a) : "l"(p));
    return a;
}
__device__ __forceinline__ void cp16(uint32_t dst, const void* src) {
    asm volatile("cp.async.cg.shared.global [%0], [%1], 16;" :: "r"(dst), "l"(src) : "memory");
}

// f16 accumulate: c = 2 regs (4 halves)
#define MMAH(c, a, bv0, bv1) \
    asm volatile("mma.sync.aligned.m16n8k16.row.col.f16.f16.f16.f16 " \
        "{%0,%1}, {%2,%3,%4,%5}, {%6,%7}, {%0,%1};" \
        : "+r"((c)[0]), "+r"((c)[1]) \
        : "r"((a)[0]), "r"((a)[1]), "r"((a)[2]), "r"((a)[3]), "r"(bv0), "r"(bv1))

#define LDMX4(r, addr) \
    asm volatile("ldmatrix.sync.aligned.m8n8.x4.shared.b16 {%0,%1,%2,%3}, [%4];" \
        : "=r"((r)[0]), "=r"((r)[1]), "=r"((r)[2]), "=r"((r)[3]) : "r"(addr))

// ---------------- prep kernels ----------------
__device__ __forceinline__ uint32_t pack_h2(float a, float b) {
    __half2 h = __floats2half2_rn(a, b);
    return *(uint32_t*)&h;
}

__global__ void vq_convert_kernel(const float* __restrict__ z, const float* __restrict__ cb) {
    const int NZ4 = NROWS * EMB / 4;
    const int NE4 = VOCAB * EMB / 4;
    int i = blockIdx.x * blockDim.x + threadIdx.x;
    if (i < NZ4) {
        float4 v = ((const float4*)z)[i];
        ((uint2*)g_zh)[i] = make_uint2(pack_h2(v.x, v.y), pack_h2(v.z, v.w));
    } else if (i < NZ4 + NE4) {
        int j = i - NZ4;
        float4 v = ((const float4*)cb)[j];
        ((uint2*)g_eh16)[j] = make_uint2(pack_h2(v.x, v.y), pack_h2(v.z, v.w));
    }
}

__global__ void vq_prep_kernel(const float* __restrict__ cb, float* __restrict__ ref_out) {
    int gtid = blockIdx.x * blockDim.x + threadIdx.x;
    int warp = gtid >> 5;
    int lane = threadIdx.x & 31;
    if (warp < VOCAB) {
        const float4* row = (const float4*)(cb + (size_t)warp * EMB);
        float4 a = row[lane];
        float4 b = row[lane + 32];
        float s = a.x*a.x + a.y*a.y + a.z*a.z + a.w*a.w
                + b.x*b.x + b.y*b.y + b.z*b.z + b.w*b.w;
        #pragma unroll
        for (int o = 16; o > 0; o >>= 1) s += __shfl_xor_sync(0xffffffffu, s, o);
        if (lane == 0) g_e_half[warp] = 0.5f * s;
    }
    if (gtid < VOCAB) ref_out[gtid] = 0.0f;
}

// ---------------- phase 1: HMMA(f16-acc) GEMM + top-candidate select -------
#define GCH     32                      // codes per chunk
#define NCHUNKS (VOCAB / GCH)           // 256
#define BBUF    16384                   // bytes per B stage (32 codes x 512B)
#define SM_EH   49152                   // after 3 B stages
#define SMEM_GB (SM_EH + VOCAB * 4)     // 81920

#define TOP2(s_, c_, v1, i1, v2, i2) { float _t = (s_); \
    if (_t > (v2)) { if (_t > (v1)) { (v2)=(v1); (i2)=(i1); (v1)=_t; (i1)=(c_); } \
                     else          { (v2)=_t;  (i2)=(c_); } } }

#define INS4(s_, c_) { float _u = (s_); int _d = (c_); \
    if (_u > w3) { \
        if (_u > w1) { \
            if (_u > w0) { w3=w2;q3=q2; w2=w1;q2=q1; w1=w0;q1=q0; w0=_u;q0=_d; } \
            else         { w3=w2;q3=q2; w2=w1;q2=q1; w1=_u;q1=_d; } \
        } else { \
            if (_u > w2) { w3=w2;q3=q2; w2=_u;q2=_d; } \
            else         { w3=_u;q3=_d; } \
        } } }

__global__ void __launch_bounds__(128, 1) vq_gemm_kernel() {
    extern __shared__ char sm[];
    const uint32_t sb = smem_u32(sm);
    const int tid  = threadIdx.x;
    const int lane = tid & 31;
    const int warp = tid >> 5;
    const int blk  = blockIdx.x;

    // ---- stage this CTA's 128 z rows (512B each) swizzled into smem ----
    {
        const char* src = (const char*)g_zh + (size_t)blk * 128 * 512;
        #pragma unroll
        for (int j = 0; j < 32; ++j) {
            int u = tid + j * 128;
            int n = u >> 5, g = u & 31;
            cp16(sb + n * 512 + ((g ^ (n & 7)) << 4), src + (size_t)u * 16);
        }
        asm volatile("cp.async.commit_group;" ::: "memory");
        asm volatile("cp.async.wait_group 0;" ::: "memory");
        __syncthreads();
    }

    // ---- build resident A fragments: 2 m-blocks x 16 k-blocks x 4 regs ----
    uint32_t A[2][16][4];
    {
        #pragma unroll
        for (int mb = 0; mb < 2; ++mb) {
            const int r = warp * 32 + mb * 16 + (lane & 8) + (lane & 7);
            #pragma unroll
            for (int kb = 0; kb < 16; ++kb) {
                uint32_t addr = sb + r * 512 + (((2 * kb + (lane >> 4)) ^ (lane & 7)) << 4);
                LDMX4(A[mb][kb], addr);
            }
        }
    }
    __syncthreads();   // everyone done reading z staging; smem reusable

    // ---- prologue: first two B chunks + e_half table ----
    {
        const char* src0 = (const char*)g_eh16;
        #pragma unroll
        for (int s = 0; s < 2; ++s) {
            const char* src = src0 + (size_t)s * GCH * 512;
            uint32_t dstb = sb + s * BBUF;
            #pragma unroll
            for (int j = 0; j < 8; ++j) {
                int u = tid + j * 128;
                int n = u >> 5, g = u & 31;
                cp16(dstb + n * 512 + ((g ^ (n & 7)) << 4), src + (size_t)u * 16);
            }
            asm volatile("cp.async.commit_group;" ::: "memory");
        }
        for (int i = tid; i < VOCAB; i += 128)
            *(float*)(sm + SM_EH + i * 4) = g_e_half[i];
    }

    // f16 accumulators: [mb][nb][2 regs]
    uint32_t acc[2][4][2];
    #pragma unroll
    for (int mb = 0; mb < 2; ++mb)
        #pragma unroll
        for (int nb = 0; nb < 4; ++nb) { acc[mb][nb][0] = 0u; acc[mb][nb][1] = 0u; }

    float tv1[4], tv2[4];
    int   ti1[4], ti2[4];
    #pragma unroll
    for (int s = 0; s < 4; ++s) { tv1[s] = -3.4e38f; tv2[s] = -3.4e38f; ti1[s] = 0; ti2[s] = 0; }

    // per-thread B ldmatrix address pieces (layout identical to validated R4)
    const int nbase = ((lane >> 4) & 1) * 8 + (lane & 7);
    const uint32_t brow0 = (uint32_t)nbase * 512;
    const uint32_t brow1 = (uint32_t)(nbase + 16) * 512;
    const int gb = (lane >> 3) & 1;
    const int sw = lane & 7;

    for (int ch = 0; ch < NCHUNKS; ++ch) {
        if (ch >= NCHUNKS - 1) asm volatile("cp.async.wait_group 0;" ::: "memory");
        else                   asm volatile("cp.async.wait_group 1;" ::: "memory");
        __syncthreads();

        const uint32_t bb = sb + (uint32_t)(ch % 3) * BBUF;

        #pragma unroll
        for (int kb = 0; kb < 16; ++kb) {
            uint32_t b0r[4], b1r[4];
            const uint32_t go = (uint32_t)(((2 * kb + gb) ^ sw) << 4);
            LDMX4(b0r, bb + brow0 + go);   // n-blocks 0,1
            LDMX4(b1r, bb + brow1 + go);   // n-blocks 2,3
            #pragma unroll
            for (int mb = 0; mb < 2; ++mb) {
                MMAH(acc[mb][0], A[mb][kb], b0r[0], b0r[1]);
                MMAH(acc[mb][1], A[mb][kb], b0r[2], b0r[3]);
                MMAH(acc[mb][2], A[mb][kb], b1r[0], b1r[1]);
                MMAH(acc[mb][3], A[mb][kb], b1r[2], b1r[3]);
            }
        }

        // epilogue: unpack f16 pairs, fold -0.5||e||^2, per-row top-2, reset
        const int c0 = ch * GCH + 2 * (lane & 3);
        #pragma unroll
        for (int nb = 0; nb < 4; ++nb) {
            const int ca = c0 + nb * 8;
            const float2 eh = *(const float2*)(sm + SM_EH + (size_t)ca * 4);
            #pragma unroll
            for (int mb = 0; mb < 2; ++mb) {
                const int s_ = mb * 2;
                const float2 p0 = __half22float2(*(__half2*)&acc[mb][nb][0]);
                const float2 p1 = __half22float2(*(__half2*)&acc[mb][nb][1]);
                TOP2(p0.x - eh.x, ca,     tv1[s_],     ti1[s_],     tv2[s_],     ti2[s_]);
                TOP2(p0.y - eh.y, ca + 1, tv1[s_],     ti1[s_],     tv2[s_],     ti2[s_]);
                TOP2(p1.x - eh.x, ca,     tv1[s_ + 1], ti1[s_ + 1], tv2[s_ + 1], ti2[s_ + 1]);
                TOP2(p1.y - eh.y, ca + 1, tv1[s_ + 1], ti1[s_ + 1], tv2[s_ + 1], ti2[s_ + 1]);
                acc[mb][nb][0] = 0u; acc[mb][nb][1] = 0u;
            }
        }

        // prefetch chunk ch+2
        if (ch + 2 < NCHUNKS) {
            const char* src = (const char*)g_eh16 + (size_t)(ch + 2) * GCH * 512;
            uint32_t dstb = sb + (uint32_t)((ch + 2) % 3) * BBUF;
            #pragma unroll
            for (int j = 0; j < 8; ++j) {
                int u = tid + j * 128;
                int n = u >> 5, g = u & 31;
                cp16(dstb + n * 512 + ((g ^ (n & 7)) << 4), src + (size_t)u * 16);
            }
            asm volatile("cp.async.commit_group;" ::: "memory");
        }
    }

    // ---- merge per-thread top-2 across the quad -> top-4 per row ----
    #pragma unroll
    for (int slot = 0; slot < 4; ++slot) {
        float w0 = tv1[slot], w1 = tv2[slot], w2 = -3.4e38f, w3 = -3.4e38f;
        int   q0 = ti1[slot], q1 = ti2[slot], q2 = 0, q3 = 0;
        #pragma unroll
        for (int d = 1; d <= 2; d <<= 1) {
            float o0 = __shfl_xor_sync(0xffffffffu, w0, d);
            float o1 = __shfl_xor_sync(0xffffffffu, w1, d);
            float o2 = __shfl_xor_sync(0xffffffffu, w2, d);
            float o3 = __shfl_xor_sync(0xffffffffu, w3, d);
            int   p0 = __shfl_xor_sync(0xffffffffu, q0, d);
            int   p1 = __shfl_xor_sync(0xffffffffu, q1, d);
            int   p2 = __shfl_xor_sync(0xffffffffu, q2, d);
            int   p3 = __shfl_xor_sync(0xffffffffu, q3, d);
            INS4(o0, p0); INS4(o1, p1); INS4(o2, p2); INS4(o3, p3);
        }
        if ((lane & 3) == 0) {
            const int row = blk * 128 + warp * 32 + slot * 8 + (lane >> 2);
            g_cand[row * 4 + 0] = q0;
            g_cand[row * 4 + 1] = q1;
            g_cand[row * 4 + 2] = q2;
            g_cand[row * 4 + 3] = q3;
        }
    }
}

// ---------------- phase 2: exact fp32 rescore + outputs --------------------
__global__ void __launch_bounds__(256) vq_rescore_kernel(
    const float* __restrict__ z, const float* __restrict__ cb,
    float* __restrict__ tok, float* __restrict__ zq, float* __restrict__ ref) {
    const int warp = threadIdx.x >> 5, lane = threadIdx.x & 31;
    const int row  = blockIdx.x * 8 + warp;

    int cand[4];
    #pragma unroll
    for (int k = 0; k < 4; ++k) cand[k] = g_cand[row * 4 + k];

    const float4* zr = (const float4*)(z + (size_t)row * EMB);
    const float4 z0 = zr[lane * 2], z1 = zr[lane * 2 + 1];

    float4 e0[4], e1[4];
    #pragma unroll
    for (int k = 0; k < 4; ++k) {
        const float4* er = (const float4*)(cb + (size_t)cand[k] * EMB);
        e0[k] = er[lane * 2];
        e1[k] = er[lane * 2 + 1];
    }
    float eh[4];
    #pragma unroll
    for (int k = 0; k < 4; ++k) eh[k] = g_e_half[cand[k]];

    float best = -3.4e38f;
    int   bi   = 0x7fffffff;
    #pragma unroll
    for (int k = 0; k < 4; ++k) {
        float d = z0.x*e0[k].x + z0.y*e0[k].y + z0.z*e0[k].z + z0.w*e0[k].w
                + z1.x*e1[k].x + z1.y*e1[k].y + z1.z*e1[k].z + z1.w*e1[k].w;
        #pragma unroll
        for (int o = 16; o > 0; o >>= 1) d += __shfl_xor_sync(0xffffffffu, d, o);
        const float s = d - eh[k];
        const int   c = cand[k];
        if (s > best || (s == best && c < bi)) { best = s; bi = c; }
    }
    tok[row] = (float)bi;
    if (lane == 0) atomicAdd(&ref[bi], 1.0f);
    const float4* eb = (const float4*)(cb + (size_t)bi * EMB);
    float4* o = (float4*)(zq + (size_t)row * EMB);
    o[lane * 2]     = eb[lane * 2];
    o[lane * 2 + 1] = eb[lane * 2 + 1];
}

// ---------------- launch ----------------------------------------------------
extern "C" void kernel_launch(void* const* d_in, const int* in_sizes, int n_in,
                              void* d_out, int out_size) {
    const float* z;
    const float* cb;
    if (in_sizes[0] == NROWS * EMB) { z = (const float*)d_in[0]; cb = (const float*)d_in[1]; }
    else                            { z = (const float*)d_in[1]; cb = (const float*)d_in[0]; }

    float* out = (float*)d_out;
    float* tok = out;
    float* zq  = out + NROWS;
    float* ref = out + NROWS + (size_t)NROWS * EMB;

    cudaFuncSetAttribute(vq_gemm_kernel, cudaFuncAttributeMaxDynamicSharedMemorySize, SMEM_GB);

    const int nconv = (NROWS * EMB / 4) + (VOCAB * EMB / 4);
    vq_convert_kernel<<<(nconv + 255) / 256, 256>>>(z, cb);
    vq_prep_kernel<<<(VOCAB * 32) / 256, 256>>>(cb, ref);
    vq_gemm_kernel<<<NROWS / 128, 128, SMEM_GB>>>();
    vq_rescore_kernel<<<NROWS / 8, 256>>>(z, cb, tok, zq, ref);
}